// round 11
// baseline (speedup 1.0000x reference)
#include <cuda_runtime.h>
#include <math.h>

#define B_ 32
#define S_ 8192
#define CIN_ 2
#define COUT_ 1
#define W_ 64
#define M_ 16
#define P_ 24
#define NROWS (B_*W_)      /* 2048 */
#define NSPLIT 32

typedef unsigned long long u64;

// ---- f32x2 packed helpers ----
__device__ __forceinline__ u64 pack2(float a, float b) {
    u64 r; asm("mov.b64 %0, {%1,%2};" : "=l"(r) : "f"(a), "f"(b)); return r;
}
__device__ __forceinline__ u64 fma2(u64 a, u64 b, u64 c) {
    u64 d; asm("fma.rn.f32x2 %0, %1, %2, %3;" : "=l"(d) : "l"(a), "l"(b), "l"(c)); return d;
}
__device__ __forceinline__ float2 unpack2(u64 v) {
    float2 f; asm("mov.b64 {%0,%1}, %2;" : "=f"(f.x), "=f"(f.y) : "l"(v)); return f;
}

// -------- scratch (device globals; no allocation allowed) --------
__device__ float g_h[NROWS * S_];            // 64 MB
__device__ float g_F[S_ * 32];               // [s][j]: j<16 cos, j>=16 sin
__device__ float g_part[NSPLIT * NROWS * 32];// split-K partials (8 MB)
__device__ float g_xf[NROWS * 32];           // reduced DFT coeffs
__device__ float g_ar[B_ * W_ * M_];
__device__ float g_ai[B_ * W_ * M_];

// ---------------------------------------------------------------
__global__ void k_compute_F() {
    int idx = blockIdx.x * blockDim.x + threadIdx.x;
    if (idx >= S_ * M_) return;
    int s = idx / M_, k = idx % M_;
    int r = (s * k) % S_;
    float c, sn;
    sincospif((float)r / 4096.0f, &sn, &c);
    g_F[s * 32 + k]      = c;
    g_F[s * 32 + 16 + k] = sn;
}

// ---------------------------------------------------------------
__global__ __launch_bounds__(256) void k_lift(
    const float* __restrict__ x, const float* __restrict__ fc0_w,
    const float* __restrict__ fc0_b)
{
    int s = blockIdx.x * 256 + threadIdx.x;
    int b = blockIdx.y;
    float2 xv = *(const float2*)&x[(b * S_ + s) * 2];
#pragma unroll
    for (int w = 0; w < W_; w++) {
        float v = xv.x * __ldg(&fc0_w[w * 2]) + xv.y * __ldg(&fc0_w[w * 2 + 1]) + __ldg(&fc0_b[w]);
        g_h[(b * W_ + w) * S_ + s] = v;
    }
}

// ---------------------------------------------------------------
// fwd DFT split-K. 128 threads, 256 rows/block.
// thread: jq = tid&3 (8 j = jq*8..+7), ty = tid>>2 (rows ty + 32r, r<8).
#define KT 32
#define DROWS 256
__global__ __launch_bounds__(128) void k_dft_fwd() {
    __shared__ float sA[DROWS * 36];   // 9216 floats (even base for sB)
    __shared__ float sB[KT * 32];
    int tid = threadIdx.x;
    int jq = tid & 3;        // j octet
    int ty = tid >> 2;       // row group, 0..31
    int row0 = blockIdx.x * DROWS;
    int split = blockIdx.y;

    u64 acc2[8][4];
#pragma unroll
    for (int r = 0; r < 8; r++)
#pragma unroll
        for (int t = 0; t < 4; t++) acc2[r][t] = 0ULL;

    const int KSPLIT = S_ / NSPLIT;   // 256
    for (int kt = 0; kt < KSPLIT / KT; kt++) {
        int k0 = split * KSPLIT + kt * KT;
        // sA: 256 rows x 32 cols = 2048 float4, 16 per thread
        for (int e4 = tid; e4 < 2048; e4 += 128) {
            int row = e4 >> 3, c4 = (e4 & 7) * 4;
            *(float4*)&sA[row * 36 + c4] =
                *(const float4*)&g_h[(size_t)(row0 + row) * S_ + k0 + c4];
        }
        // sB: 32x32 = 256 float4, 2 per thread
        for (int e4 = tid; e4 < 256; e4 += 128) {
            int kk = e4 >> 3, j4 = (e4 & 7) * 4;
            *(float4*)&sB[kk * 32 + j4] = *(const float4*)&g_F[(k0 + kk) * 32 + j4];
        }
        __syncthreads();
#pragma unroll
        for (int kk = 0; kk < KT; kk++) {
            u64 bt[4];
#pragma unroll
            for (int t = 0; t < 4; t++)
                bt[t] = *(const u64*)&sB[kk * 32 + jq * 8 + 2 * t];
#pragma unroll
            for (int r = 0; r < 8; r++) {
                float a = sA[(ty + 32 * r) * 36 + kk];
                u64 ad = pack2(a, a);
#pragma unroll
                for (int t = 0; t < 4; t++)
                    acc2[r][t] = fma2(bt[t], ad, acc2[r][t]);
            }
        }
        __syncthreads();
    }
#pragma unroll
    for (int r = 0; r < 8; r++) {
        float2 p0 = unpack2(acc2[r][0]);
        float2 p1 = unpack2(acc2[r][1]);
        float2 p2 = unpack2(acc2[r][2]);
        float2 p3 = unpack2(acc2[r][3]);
        size_t base = (size_t)(split * NROWS + row0 + ty + 32 * r) * 32 + jq * 8;
        *(float4*)&g_part[base]     = make_float4(p0.x, p0.y, p1.x, p1.y);
        *(float4*)&g_part[base + 4] = make_float4(p2.x, p2.y, p3.x, p3.y);
    }
}

// ---------------------------------------------------------------
// reduce split-K partials: g_xf[row][j] = sum_sp g_part[sp][row][j]
__global__ __launch_bounds__(256) void k_reduce() {
    int idx = blockIdx.x * 256 + threadIdx.x;   // 0..16383
    int row = idx >> 3;
    int c4 = (idx & 7) * 4;
    float4 s = make_float4(0.f, 0.f, 0.f, 0.f);
#pragma unroll
    for (int sp = 0; sp < NSPLIT; sp++) {
        float4 v = *(const float4*)&g_part[(size_t)(sp * NROWS + row) * 32 + c4];
        s.x += v.x; s.y += v.y; s.z += v.z; s.w += v.w;
    }
    *(float4*)&g_xf[row * 32 + c4] = s;
}

// ---------------------------------------------------------------
// spectral multiply: grid (B_, 4), 256 threads = 16 o x 16 k.
__global__ __launch_bounds__(256) void k_specmul(
    const float* __restrict__ wr, const float* __restrict__ wi, int l)
{
    __shared__ float sxr[W_ * 16];
    __shared__ float sxi[W_ * 16];
    int b = blockIdx.x;
    int o0 = blockIdx.y * 16;
    int tid = threadIdx.x;

    for (int e = tid; e < W_ * 32; e += 256) {
        int i = e >> 5, j = e & 31;
        float v = g_xf[(b * W_ + i) * 32 + j];
        if (j < 16) sxr[i * 16 + j] = v;
        else        sxi[i * 16 + j - 16] = -v;   // imag = -sum(h*sin)
    }
    __syncthreads();

    int o = o0 + (tid >> 4);
    int k = tid & 15;
    float accr = 0.f, acci = 0.f;
#pragma unroll
    for (int i = 0; i < W_; i++) {
        float xr = sxr[i * 16 + k], xi = sxi[i * 16 + k];
        float wrr = __ldg(&wr[((l * W_ + i) * W_ + o) * M_ + k]);
        float wii = __ldg(&wi[((l * W_ + i) * W_ + o) * M_ + k]);
        accr += xr * wrr - xi * wii;
        acci += xr * wii + xi * wrr;
    }
    float sc = (k == 0 ? 1.0f : 2.0f) / (float)S_;
    g_ar[(b * W_ + o) * M_ + k] = accr * sc;
    g_ai[(b * W_ + o) * M_ + k] = acci * sc;
}

// ---------------------------------------------------------------
// layer update: 128 threads, tile 64o x 128s, thread 16o x 4s (o-pairs).
__global__ __launch_bounds__(128) void k_layer(
    const float* __restrict__ pw_w, const float* __restrict__ pw_b,
    int l, int do_relu)
{
    extern __shared__ float sm[];
    float* sh    = sm;                  // 64*128 = 8192  @0
    float* sF    = sh + 8192;           // 128*33 = 4224  @8192
    float* sWt   = sF + 4224;           // 64*66  = 4224  @12416 (even) [i][o]
    float* sar_t = sWt + 4224;          // 16*66  = 1056  @16640 (even) [k][o]
    float* sai_t = sar_t + 1056;        // 16*66  = 1056  @17696 (even) [k][o], NEGATED
    float* sb    = sai_t + 1056;        // 64             @18752

    int b = blockIdx.y;
    int s0 = blockIdx.x * 128;
    int tid = threadIdx.x;
    int tx = tid & 31;
    int ty = tid >> 5;       // 0..3
    int o0 = ty * 16;

    for (int e4 = tid; e4 < 2048; e4 += 128) {
        int w = e4 >> 5, c4 = (e4 & 31) * 4;
        *(float4*)&sh[w * 128 + c4] =
            *(const float4*)&g_h[(size_t)(b * W_ + w) * S_ + s0 + c4];
    }
    for (int e = tid; e < 4096; e += 128) {
        int s = e >> 5, j = e & 31;
        sF[s * 33 + j] = g_F[(s0 + s) * 32 + j];
    }
    // transposed pointwise weights: sWt[i*66 + o] = pw[l][o][i]
    for (int e = tid; e < 4096; e += 128) {
        int o = e >> 6, i = e & 63;
        sWt[i * 66 + o] = pw_w[l * W_ * W_ + e];
    }
    // transposed spectral coeffs: [k][o]; sai negated (folds irfft sign)
    for (int e = tid; e < W_ * M_; e += 128) {
        int o = e >> 4, k = e & 15;
        sar_t[k * 66 + o] =  g_ar[(b * W_ + o) * M_ + k];
        sai_t[k * 66 + o] = -g_ai[(b * W_ + o) * M_ + k];
    }
    if (tid < 64) sb[tid] = pw_b[l * W_ + tid];
    __syncthreads();

    u64 acc2[8][4];
#pragma unroll
    for (int rp = 0; rp < 8; rp++)
#pragma unroll
        for (int c = 0; c < 4; c++) acc2[rp][c] = 0ULL;

    // pointwise conv: 32 f32x2-FMA per i
#pragma unroll 2
    for (int i = 0; i < W_; i++) {
        u64 hd[4], wv2[8];
#pragma unroll
        for (int c = 0; c < 4; c++) {
            float hv = sh[i * 128 + tx + 32 * c];
            hd[c] = pack2(hv, hv);
        }
#pragma unroll
        for (int rp = 0; rp < 8; rp++)
            wv2[rp] = *(const u64*)&sWt[i * 66 + o0 + 2 * rp];
#pragma unroll
        for (int rp = 0; rp < 8; rp++)
#pragma unroll
            for (int c = 0; c < 4; c++)
                acc2[rp][c] = fma2(wv2[rp], hd[c], acc2[rp][c]);
    }
    // irfft from 16 modes: 64 f32x2-FMA per k
#pragma unroll
    for (int k = 0; k < M_; k++) {
        u64 fcd[4], fsd[4];
#pragma unroll
        for (int c = 0; c < 4; c++) {
            float fc = sF[(tx + 32 * c) * 33 + k];
            float fs = sF[(tx + 32 * c) * 33 + 16 + k];
            fcd[c] = pack2(fc, fc);
            fsd[c] = pack2(fs, fs);
        }
#pragma unroll
        for (int rp = 0; rp < 8; rp++) {
            u64 ar2  = *(const u64*)&sar_t[k * 66 + o0 + 2 * rp];
            u64 ain2 = *(const u64*)&sai_t[k * 66 + o0 + 2 * rp];
#pragma unroll
            for (int c = 0; c < 4; c++) {
                acc2[rp][c] = fma2(ar2,  fcd[c], acc2[rp][c]);
                acc2[rp][c] = fma2(ain2, fsd[c], acc2[rp][c]);
            }
        }
    }
#pragma unroll
    for (int rp = 0; rp < 8; rp++) {
        int oA = o0 + 2 * rp, oB = oA + 1;
        float bA = sb[oA], bB = sb[oB];
#pragma unroll
        for (int c = 0; c < 4; c++) {
            float2 v = unpack2(acc2[rp][c]);
            float vA = v.x + bA, vB = v.y + bB;
            if (do_relu) { vA = fmaxf(vA, 0.f); vB = fmaxf(vB, 0.f); }
            g_h[(size_t)(b * W_ + oA) * S_ + s0 + tx + 32 * c] = vA;
            g_h[(size_t)(b * W_ + oB) * S_ + s0 + tx + 32 * c] = vB;
        }
    }
}

// ---------------------------------------------------------------
// head: 256 threads. GEMM1 thread 16j x 4s; GEMM2 thread 12p x 1s.
__global__ __launch_bounds__(256) void k_head(
    const float* __restrict__ fc1_w, const float* __restrict__ fc1_b,
    const float* __restrict__ fc2_w, const float* __restrict__ ica_w,
    const float* __restrict__ ica_b, float* __restrict__ out,
    float* __restrict__ tc)
{
    extern __shared__ float sm[];
    float* sh     = sm;                    // 64*128   @0
    float* sfc1t  = sh + 64 * 128;         // 64*130   @8192  [w][j]
    float* sU     = sfc1t + 64 * 130;      // 128*130  @16512 [s][j]
    float* sica   = sU + 128 * 130;        // 24*128   @33152
    float* sTc    = sica + 24 * 128;       // 128*25   @36224
    float* sb1    = sTc + 128 * 25;        // 128
    float* sf2    = sb1 + 128;             // 128
    float* sib    = sf2 + 128;             // 24
    __shared__ float sred[2][128];

    int b = blockIdx.y;
    int s0 = blockIdx.x * 128;
    int tid = threadIdx.x;

    for (int e4 = tid; e4 < 2048; e4 += 256) {
        int w = e4 >> 5, c4 = (e4 & 31) * 4;
        *(float4*)&sh[w * 128 + c4] =
            *(const float4*)&g_h[(size_t)(b * W_ + w) * S_ + s0 + c4];
    }
    // transposed fc1: sfc1t[w*130 + j] = fc1_w[j][w]
    for (int e = tid; e < 8192; e += 256) {
        int j = e >> 6, w = e & 63;
        sfc1t[w * 130 + j] = fc1_w[e];
    }
    for (int e = tid; e < 24 * 128; e += 256) sica[e] = ica_w[e];
    if (tid < 128) { sb1[tid] = fc1_b[tid]; sf2[tid] = fc2_w[tid]; }
    if (tid >= 128 && tid < 152) sib[tid - 128] = ica_b[tid - 128];
    __syncthreads();

    // GEMM1: thread j0 = ty*16 (8 pairs), s = tx + 32c
    {
        int tx = tid & 31;
        int ty = tid >> 5;      // 0..7
        int j0 = ty * 16;
        u64 acc2[8][4];
#pragma unroll
        for (int rp = 0; rp < 8; rp++)
#pragma unroll
            for (int c = 0; c < 4; c++) acc2[rp][c] = 0ULL;
#pragma unroll 2
        for (int w = 0; w < 64; w++) {
            u64 hd[4], fv2[8];
#pragma unroll
            for (int c = 0; c < 4; c++) {
                float hv = sh[w * 128 + tx + 32 * c];
                hd[c] = pack2(hv, hv);
            }
#pragma unroll
            for (int rp = 0; rp < 8; rp++)
                fv2[rp] = *(const u64*)&sfc1t[w * 130 + j0 + 2 * rp];
#pragma unroll
            for (int rp = 0; rp < 8; rp++)
#pragma unroll
                for (int c = 0; c < 4; c++)
                    acc2[rp][c] = fma2(fv2[rp], hd[c], acc2[rp][c]);
        }
#pragma unroll
        for (int rp = 0; rp < 8; rp++) {
            int jA = j0 + 2 * rp, jB = jA + 1;
            float bA = sb1[jA], fA = sf2[jA];
            float bB = sb1[jB], fB = sf2[jB];
#pragma unroll
            for (int c = 0; c < 4; c++) {
                float2 v = unpack2(acc2[rp][c]);
                float uA = fmaxf(v.x + bA, 0.f) * fA;
                float uB = fmaxf(v.y + bB, 0.f) * fB;
                *(u64*)&sU[(tx + 32 * c) * 130 + jA] = pack2(uA, uB);
            }
        }
    }
    __syncthreads();

    // GEMM2: thread: s = tid&127, pq = tid>>7 (0..1), p = pq + 2q, q<12
    {
        int s = tid & 127;
        int pq = tid >> 7;
        u64 a2[12];
#pragma unroll
        for (int q = 0; q < 12; q++) a2[q] = 0ULL;
#pragma unroll 4
        for (int jp = 0; jp < 64; jp++) {
            u64 uv2 = *(const u64*)&sU[s * 130 + 2 * jp];
#pragma unroll
            for (int q = 0; q < 12; q++) {
                u64 wv = *(const u64*)&sica[(pq + 2 * q) * 128 + 2 * jp];
                a2[q] = fma2(wv, uv2, a2[q]);
            }
        }
        float psum = 0.f;
#pragma unroll
        for (int q = 0; q < 12; q++) {
            int p = pq + 2 * q;
            float2 f = unpack2(a2[q]);
            float v = f.x + f.y + sib[p];
            sTc[s * 25 + p] = v;
            psum += v;
        }
        sred[pq][s] = psum;
    }
    __syncthreads();

    float* tc_base = tc + (size_t)(b * S_ + s0) * P_;
    for (int e = tid; e < 128 * P_; e += 256) {
        int s = e / P_, p = e % P_;
        tc_base[e] = sTc[s * 25 + p];
    }
    if (tid < 128)
        out[(size_t)b * S_ + s0 + tid] = sred[0][tid] + sred[1][tid];
}

// ---------------------------------------------------------------
extern "C" void kernel_launch(void* const* d_in, const int* in_sizes, int n_in,
                              void* d_out, int out_size) {
    (void)in_sizes; (void)n_in; (void)out_size;
    const float* x       = (const float*)d_in[0];
    const float* fc0_w   = (const float*)d_in[1];
    const float* fc0_b   = (const float*)d_in[2];
    const float* conv_wr = (const float*)d_in[3];
    const float* conv_wi = (const float*)d_in[4];
    const float* pw_w    = (const float*)d_in[5];
    const float* pw_b    = (const float*)d_in[6];
    const float* fc1_w   = (const float*)d_in[7];
    const float* fc1_b   = (const float*)d_in[8];
    const float* fc2_w   = (const float*)d_in[9];
    const float* ica_w   = (const float*)d_in[10];
    const float* ica_b   = (const float*)d_in[11];

    float* out = (float*)d_out;
    float* tc  = out + (size_t)B_ * S_ * COUT_;

    const int LAY_SMEM  = (8192 + 4224 + 4224 + 1056 + 1056 + 64) * 4;             // 75264 B
    const int HEAD_SMEM = (64*128 + 64*130 + 128*130 + 24*128 + 128*25 + 280) * 4; // 158816 B
    cudaFuncSetAttribute(k_layer, cudaFuncAttributeMaxDynamicSharedMemorySize, LAY_SMEM);
    cudaFuncSetAttribute(k_head,  cudaFuncAttributeMaxDynamicSharedMemorySize, HEAD_SMEM);

    k_compute_F<<<(S_ * M_ + 255) / 256, 256>>>();
    k_lift<<<dim3(S_ / 256, B_), 256>>>(x, fc0_w, fc0_b);

    for (int l = 0; l < 4; l++) {
        k_dft_fwd<<<dim3(NROWS / DROWS, NSPLIT), 128>>>();
        k_reduce<<<64, 256>>>();
        k_specmul<<<dim3(B_, 4), 256>>>(conv_wr, conv_wi, l);
        k_layer<<<dim3(S_ / 128, B_), 128, LAY_SMEM>>>(pw_w, pw_b, l, (l < 3) ? 1 : 0);
    }

    k_head<<<dim3(S_ / 128, B_), 256, HEAD_SMEM>>>(fc1_w, fc1_b, fc2_w, ica_w, ica_b, out, tc);
}